// round 17
// baseline (speedup 1.0000x reference)
#include <cuda_runtime.h>
#include <cstdint>

#define NP 256
#define NG 1024
#define F  128
#define EPSV 1e-5f

#define TP 32
#define TG 32
#define KC 64          // 2 chunks

// ---------------- f32x2 helpers ----------------
__device__ __forceinline__ unsigned long long fma2(unsigned long long a,
                                                   unsigned long long b,
                                                   unsigned long long c) {
    unsigned long long d;
    asm("fma.rn.f32x2 %0, %1, %2, %3;" : "=l"(d) : "l"(a), "l"(b), "l"(c));
    return d;
}
__device__ __forceinline__ unsigned long long dup2(float x) {
    unsigned long long d;
    asm("mov.b64 %0, {%1, %1};" : "=l"(d) : "f"(x));
    return d;
}
__device__ __forceinline__ float2 unpack2(unsigned long long v) {
    float2 r;
    asm("mov.b64 {%0, %1}, %2;" : "=f"(r.x), "=f"(r.y) : "l"(v));
    return r;
}

// ---------------- fused kernel: 32x32 tile, 256 blocks -> ~2 blocks/SM ----------------
// out[p,g,c] = A[p,c] + B[g,c] + K[c] - 2 * sum_f (p_f * w'_cf) * g_f
// Acc f32x2 lanes = (g, g+1); probe operands duplicated into smem at store time.
// Mainloop: 3 LDS + 4 FFMA2 per f. Full LDG prefetch overlaps the prologue.
__global__ void __launch_bounds__(256, 2) cls_kernel(
    const float* __restrict__ probe, const float* __restrict__ gal,
    const float* __restrict__ bnw, const float* __restrict__ bnb,
    const float* __restrict__ bnm, const float* __restrict__ bnv,
    const float* __restrict__ W, const float* __restrict__ bias,
    float* __restrict__ out)
{
    // sPd row = 66 u64 = 528 B (33*16); sG row = 36 fl = 144 B (9*16).
    // sPd size 65*66*8 = 34320 B; sG 65*36*4 = 9360 B -> ~44 KB static.
    __shared__ __align__(16) unsigned long long sPd[KC + 1][2 * TP + 2]; // [f][2p+c] dup'd
    __shared__ __align__(16) float sG[KC + 1][TG + 4];                   // [f][g] raw
    __shared__ float2 sA[TP];
    __shared__ float2 sB[TG];

    const int tid  = threadIdx.x;
    const int lane = tid & 31;
    const int warp = tid >> 5;      // 0..7
    const int bp = blockIdx.y * TP;
    const int bg = blockIdx.x * TG;

    // ======== PREFETCH: all 32 data LDGs up-front (latency overlaps prologue) ========
    float px[2][4][2];   // [chunk][k][half]: probe row p = warp + 8k, f = c*KC + lane(+32)
    float gx[2][4][2];   // [chunk][k][half]: gallery row g = warp + 8k
    #pragma unroll
    for (int c = 0; c < 2; c++) {
        #pragma unroll
        for (int k = 0; k < 4; k++) {
            const float* srcp = probe + (size_t)(bp + warp + 8 * k) * F + c * KC;
            px[c][k][0] = srcp[lane];
            px[c][k][1] = srcp[lane + 32];
            const float* srcg = gal + (size_t)(bg + warp + 8 * k) * F + c * KC;
            gx[c][k][0] = srcg[lane];
            gx[c][k][1] = srcg[lane + 32];
        }
    }

    // -------- folded weights (lane f-stripe: f = lane + 32i) + K reduction --------
    float w0r[4], w1r[4];
    float kc0 = 0.f, kc1 = 0.f;
    #pragma unroll
    for (int i = 0; i < 4; i++) {
        const int f = lane + 32 * i;
        const float inv = bnw[f] * rsqrtf(bnv[f] + EPSV);
        const float Wf0 = W[f], Wf1 = W[F + f];
        w0r[i] = Wf0 * inv;
        w1r[i] = Wf1 * inv;
        const float off = bnb[f] - bnm[f] * inv;
        kc0 = fmaf(Wf0, off, kc0);
        kc1 = fmaf(Wf1, off, kc1);
    }
    #pragma unroll
    for (int o = 16; o > 0; o >>= 1) {
        kc0 += __shfl_xor_sync(0xffffffffu, kc0, o);
        kc1 += __shfl_xor_sync(0xffffffffu, kc1, o);
    }
    kc0 += bias[0];
    kc1 += bias[1];

    // -------- thread mapping: 2 probes x 2 gallery x 2 classes --------
    const int ty = tid >> 4;      // 0..15 -> probe pair
    const int tx = tid & 15;      // 0..15 -> gallery pair
    const int tp = 2 * ty;
    const int tg = 2 * tx;

    unsigned long long A0 = 0, A1 = 0;   // probe tp   : class0 / class1 @ (g, g+1)
    unsigned long long B0 = 0, B1 = 0;   // probe tp+1

    float pa0[4], pa1[4];
    float gb0[4], gb1[4];
    #pragma unroll
    for (int k = 0; k < 4; k++) { pa0[k] = 0.f; pa1[k] = 0.f; gb0[k] = 0.f; gb1[k] = 0.f; }

    #pragma unroll
    for (int c = 0; c < 2; c++) {
        // ---- probes: scale + DUPLICATE from registers into smem; fused A partials ----
        #pragma unroll
        for (int k = 0; k < 4; k++) {
            const int p = warp + 8 * k;
            const float x0 = px[c][k][0];
            const float x1 = px[c][k][1];
            const float s00 = x0 * w0r[2 * c],     s01 = x0 * w1r[2 * c];
            const float s10 = x1 * w0r[2 * c + 1], s11 = x1 * w1r[2 * c + 1];
            *(ulonglong2*)&sPd[lane][2 * p]      = make_ulonglong2(dup2(s00), dup2(s01));
            *(ulonglong2*)&sPd[lane + 32][2 * p] = make_ulonglong2(dup2(s10), dup2(s11));
            pa0[k] = fmaf(s00, x0, fmaf(s10, x1, pa0[k]));
            pa1[k] = fmaf(s01, x0, fmaf(s11, x1, pa1[k]));
        }
        // ---- gallery: store raw from registers; fused B partials ----
        #pragma unroll
        for (int k = 0; k < 4; k++) {
            const int g = warp + 8 * k;
            const float x0 = gx[c][k][0];
            const float x1 = gx[c][k][1];
            sG[lane][g]      = x0;
            sG[lane + 32][g] = x1;
            gb0[k] = fmaf(w0r[2 * c] * x0, x0, fmaf(w0r[2 * c + 1] * x1, x1, gb0[k]));
            gb1[k] = fmaf(w1r[2 * c] * x0, x0, fmaf(w1r[2 * c + 1] * x1, x1, gb1[k]));
        }
        __syncthreads();

        // ---- mainloop: 3 LDS + 4 FFMA2 per f, zero MOVs ----
        ulonglong2 Pa = *(const ulonglong2*)&sPd[0][2 * tp];       // probe tp : (c0d, c1d)
        ulonglong2 Pb = *(const ulonglong2*)&sPd[0][2 * tp + 2];   // probe tp+1
        unsigned long long G = *(const unsigned long long*)&sG[0][tg];  // (g, g+1)
        #pragma unroll 8
        for (int f = 0; f < KC; f++) {
            const ulonglong2 Pan = *(const ulonglong2*)&sPd[f + 1][2 * tp];     // row KC = pad
            const ulonglong2 Pbn = *(const ulonglong2*)&sPd[f + 1][2 * tp + 2];
            const unsigned long long Gn = *(const unsigned long long*)&sG[f + 1][tg];
            A0 = fma2(Pa.x, G, A0);
            A1 = fma2(Pa.y, G, A1);
            B0 = fma2(Pb.x, G, B0);
            B1 = fma2(Pb.y, G, B1);
            Pa = Pan; Pb = Pbn; G = Gn;
        }
        __syncthreads();
    }

    // -------- reduce A/B partials across lanes into smem --------
    #pragma unroll
    for (int k = 0; k < 4; k++) {
        float r0 = pa0[k], r1 = pa1[k];
        float s0 = gb0[k], s1 = gb1[k];
        #pragma unroll
        for (int o = 16; o > 0; o >>= 1) {
            r0 += __shfl_down_sync(0xffffffffu, r0, o);
            r1 += __shfl_down_sync(0xffffffffu, r1, o);
            s0 += __shfl_down_sync(0xffffffffu, s0, o);
            s1 += __shfl_down_sync(0xffffffffu, s1, o);
        }
        if (lane == 0) {
            sA[warp + 8 * k] = make_float2(r0, r1);
            sB[warp + 8 * k] = make_float2(s0, s1);
        }
    }
    __syncthreads();

    // -------- epilogue: 8 outputs per thread --------
    const float2 B0v = sB[tg];
    const float2 B1v = sB[tg + 1];

    #pragma unroll
    for (int i = 0; i < 2; i++) {
        const float2 Ap = sA[tp + i];
        const float ax = Ap.x + kc0;
        const float ay = Ap.y + kc1;
        const float2 c0 = unpack2(i == 0 ? A0 : B0);   // class0 @ (g, g+1)
        const float2 c1 = unpack2(i == 0 ? A1 : B1);   // class1 @ (g, g+1)
        float4 o;
        o.x = fmaf(-2.0f, c0.x, ax + B0v.x);
        o.y = fmaf(-2.0f, c1.x, ay + B0v.y);
        o.z = fmaf(-2.0f, c0.y, ax + B1v.x);
        o.w = fmaf(-2.0f, c1.y, ay + B1v.y);
        *(float4*)(out + ((size_t)(bp + tp + i) * NG + bg + tg) * 2) = o;
    }
}

// ---------------- launch: ONE kernel ----------------
extern "C" void kernel_launch(void* const* d_in, const int* in_sizes, int n_in,
                              void* d_out, int out_size) {
    const float* probe = (const float*)d_in[0];
    const float* gal   = (const float*)d_in[1];
    const float* bnw   = (const float*)d_in[2];
    const float* bnb   = (const float*)d_in[3];
    const float* bnm   = (const float*)d_in[4];
    const float* bnv   = (const float*)d_in[5];
    const float* W     = (const float*)d_in[6];
    const float* bias  = (const float*)d_in[7];
    float* out = (float*)d_out;

    dim3 grid(NG / TG, NP / TP);   // (32, 8) = 256 blocks x 256 threads -> ~2 blocks/SM
    cls_kernel<<<grid, 256>>>(probe, gal, bnw, bnb, bnm, bnv, W, bias, out);
}